// round 7
// baseline (speedup 1.0000x reference)
#include <cuda_runtime.h>

#define WIMG 128
#define HIMG 128
#define NV   512
#define NF   1024
#define NPIX (WIMG * HIMG)
#define EMPTY_KEY 0xFFFFFFFFFFFFFFFFull

// ---- scratch (no allocations allowed) ----
__device__ float4 g_tri0[NF];   // (bbox_u32, area, inv_area, za)
__device__ float4 g_tri1[NF];   // (ax, ay, bx, by)
__device__ float4 g_tri2[NF];   // (cx, cy, zb, zc)
__device__ float  g_iw[NV];
__device__ unsigned long long g_best[NPIX];

__device__ __forceinline__ float fm(float a, float b) { return __fmul_rn(a, b); }
__device__ __forceinline__ float fa(float a, float b) { return __fadd_rn(a, b); }
__device__ __forceinline__ float fs(float a, float b) { return __fsub_rn(a, b); }
__device__ __forceinline__ float fd(float a, float b) { return __fdiv_rn(a, b); }
__device__ __forceinline__ float ff3(float a, float b, float c) { return __fmaf_rn(a, b, c); }

// XLA-contracted edge/area form: a*b - c*d  ->  fma(a, b, -(c*d))
__device__ __forceinline__ float edge_fn(float a, float b, float c, float d) {
    return ff3(a, b, -fm(c, d));
}

// ======================= setup: one block, 512 threads =======================
__global__ void setup_kernel(const float* __restrict__ v,
                             const int* __restrict__ f,
                             const float* __restrict__ cf,
                             const float* __restrict__ cc,
                             const float* __restrict__ ct,
                             const float* __restrict__ crt) {
    __shared__ float sxs[NV], sys[NV], szn[NV];
    int t = threadIdx.x;

    // init per-pixel winner keys (32 per thread)
    #pragma unroll
    for (int k = t; k < NPIX; k += 512) g_best[k] = EMPTY_KEY;

    // ---- camera matrix (redundant per thread; cheap) ----
    float rx = crt[0], ry = crt[1], rz = crt[2];
    float ssq = fa(fa(fm(rx, rx), fm(ry, ry)), fm(rz, rz));
    float theta = __fsqrt_rn(fa(ssq, 1e-12f));
    float kx = fd(rx, theta), ky = fd(ry, theta), kz = fd(rz, theta);
    float K[3][3] = {{0.f, -kz, ky}, {kz, 0.f, -kx}, {-ky, kx, 0.f}};
    float KK[3][3];
    #pragma unroll
    for (int i = 0; i < 3; i++)
        #pragma unroll
        for (int j = 0; j < 3; j++) {
            float s = fm(K[i][0], K[0][j]);
            s = ff3(K[i][1], K[1][j], s);
            s = ff3(K[i][2], K[2][j], s);
            KK[i][j] = s;
        }
    float sth = sinf(theta), cth1 = fs(1.0f, cosf(theta));
    float R[3][3];
    #pragma unroll
    for (int i = 0; i < 3; i++)
        #pragma unroll
        for (int j = 0; j < 3; j++) {
            float e = (i == j) ? 1.0f : 0.0f;
            R[i][j] = ff3(cth1, KK[i][j], ff3(sth, K[i][j], e));
        }
    float Mr[4][4] = {{0}}, Mt[4][4] = {{0}};
    #pragma unroll
    for (int i = 0; i < 4; i++) { Mr[i][i] = 1.f; Mt[i][i] = 1.f; }
    #pragma unroll
    for (int i = 0; i < 3; i++)
        #pragma unroll
        for (int j = 0; j < 3; j++) Mr[i][j] = R[j][i];
    Mt[3][0] = ct[0]; Mt[3][1] = ct[1]; Mt[3][2] = ct[2];
    float Vw[4][4];
    #pragma unroll
    for (int i = 0; i < 4; i++)
        #pragma unroll
        for (int j = 0; j < 4; j++) {
            float s = fm(Mr[i][0], Mt[0][j]);
            s = ff3(Mr[i][1], Mt[1][j], s);
            s = ff3(Mr[i][2], Mt[2][j], s);
            s = ff3(Mr[i][3], Mt[3][j], s);
            Vw[i][j] = s;
        }
    float ffv = fm(0.5f, fa(cf[0], cf[1]));
    float nf = fd(0.1f, ffv);
    float cx0 = fa(cc[0], 0.5f);
    float right  = fm(fs(128.0f, cx0), nf);
    float left   = -fm(cx0, nf);
    float top    = fm(fa(cc[1], 0.5f), nf);
    float bottom = -fm(fa(fs(128.0f, cc[1]), 0.5f), nf);
    float P[4][4] = {{0}};
    P[0][0] = fd(0.2f, fs(right, left));
    P[1][1] = fd(0.2f, fs(top, bottom));
    P[2][0] = fd(fa(right, left), fs(right, left));
    P[2][1] = fd(fa(top, bottom), fs(top, bottom));
    P[2][2] = (float)(-(10.0 + 0.1) / (10.0 - 0.1));
    P[2][3] = -1.0f;
    P[3][2] = (float)(-2.0 * 10.0 * 0.1 / (10.0 - 0.1));
    float M[4][4];
    #pragma unroll
    for (int i = 0; i < 4; i++)
        #pragma unroll
        for (int j = 0; j < 4; j++) {
            float s = fm(Vw[i][0], P[0][j]);
            s = ff3(Vw[i][1], P[1][j], s);
            s = ff3(Vw[i][2], P[2][j], s);
            s = ff3(Vw[i][3], P[3][j], s);
            M[i][j] = s;
        }

    // ---- vertex transform (1 per thread) ----
    if (t < NV) {
        float vx = v[3 * t], vy = v[3 * t + 1], vz = v[3 * t + 2];
        float c[4];
        #pragma unroll
        for (int j = 0; j < 4; j++) {
            float s = fm(vx, M[0][j]);
            s = ff3(vy, M[1][j], s);
            s = ff3(vz, M[2][j], s);
            s = ff3(1.0f, M[3][j], s);
            c[j] = s;
        }
        int vld = (c[3] > 1e-8f) ? 1 : 0;
        float ws = vld ? c[3] : 1.0f;
        float nx = fd(c[0], ws), ny = fd(c[1], ws), nz = fd(c[2], ws);
        sxs[t] = fm(ff3(nx, 0.5f, 0.5f), 128.0f);   // pow2 scales: exact
        sys[t] = fm(fs(0.5f, fm(ny, 0.5f)), 128.0f);
        szn[t] = vld ? nz : __int_as_float(0x7FC00000);  // NaN marks invalid
        g_iw[t] = fd(1.0f, ws);
    }
    __syncthreads();

    // ---- triangle setup (2 per thread) ----
    for (int k = t; k < NF; k += 512) {
        int i0 = f[3 * k], i1 = f[3 * k + 1], i2 = f[3 * k + 2];
        float ax = sxs[i0], ay = sys[i0];
        float bx = sxs[i1], by = sys[i1];
        float cx = sxs[i2], cy = sys[i2];
        float area = edge_fn(fs(bx, ax), fs(cy, ay), fs(by, ay), fs(cx, ax));
        float za = szn[i0], zb = szn[i1], zc = szn[i2];
        bool zok = (za == za) && (zb == zb) && (zc == zc);   // verts valid
        bool ok = zok && (fabsf(area) > 1e-8f);
        float nanf = __int_as_float(0x7FC00000);
        float area_s = ok ? area : nanf;        // poisons exact path
        float ia     = ok ? fd(1.0f, area) : nanf;

        // conservative pixel-space bbox (u8x4); 255 in ixlo => always cull
        unsigned int packed = 255u;
        if (ok) {
            float xmin = fminf(ax, fminf(bx, cx));
            float xmax = fmaxf(ax, fmaxf(bx, cx));
            float ymin = fminf(ay, fminf(by, cy));
            float ymax = fmaxf(ay, fmaxf(by, cy));
            if (!(xmax < 0.5f || xmin > 127.5f || ymax < 0.5f || ymin > 127.5f)) {
                int ixlo = (int)floorf(fminf(fmaxf(xmin - 0.5f, 0.f), 127.f));
                int ixhi = (int)ceilf (fminf(fmaxf(xmax - 0.5f, 0.f), 127.f));
                int iylo = (int)floorf(fminf(fmaxf(ymin - 0.5f, 0.f), 127.f));
                int iyhi = (int)ceilf (fminf(fmaxf(ymax - 0.5f, 0.f), 127.f));
                packed = (unsigned)ixlo | ((unsigned)ixhi << 8) |
                         ((unsigned)iylo << 16) | ((unsigned)iyhi << 24);
            }
        }
        g_tri0[k] = make_float4(__uint_as_float(packed), area_s, ia, za);
        g_tri1[k] = make_float4(ax, ay, bx, by);
        g_tri2[k] = make_float4(cx, cy, zb, zc);
    }
}

// order-preserving float key: ascending float -> ascending uint
__device__ __forceinline__ unsigned int zkey(float z) {
    unsigned int b = __float_as_uint(z);
    return (b & 0x80000000u) ? ~b : (b | 0x80000000u);
}

// ======================= raster: 1024 blocks x 128 ===========================
// block b: pixel group pg = b>>1 (32 pixels, one per lane);
// warp wi handles triangle chunk ((b&1)<<2)|wi of 128 triangles.
__global__ void __launch_bounds__(128) raster_kernel() {
    int t = threadIdx.x;
    int wi = t >> 5, lane = t & 31;
    int pg = blockIdx.x >> 1;
    int chunk = ((blockIdx.x & 1) << 2) | wi;
    int bx0 = 32 * (pg & 3);
    int iy  = pg >> 2;
    int pid = pg * 32 + lane;                   // == row-major pixel index
    float x = (float)(bx0 + lane) + 0.5f;
    float y = (float)iy + 0.5f;

    float bd = __int_as_float(0x7f800000);      // +inf
    int   bi = 0x7fffffff;

    int base = chunk * (NF / 8);
    #pragma unroll 4
    for (int i = 0; i < NF / 8; ++i) {
        int idx = base + i;                     // warp-uniform
        float4 p0 = __ldg(&g_tri0[idx]);
        unsigned int bb = __float_as_uint(p0.x);
        int ixlo = bb & 255, ixhi = (bb >> 8) & 255;
        int iylo = (bb >> 16) & 255, iyhi = (bb >> 24) & 255;
        if (ixhi < bx0 || ixlo > bx0 + 31 || iyhi < iy || iylo > iy) continue;

        float area = p0.y, ia = p0.z, za = p0.w;
        float4 p1 = __ldg(&g_tri1[idx]);
        float4 p2 = __ldg(&g_tri2[idx]);
        float ax = p1.x, ay = p1.y, bxv = p1.z, byv = p1.w;
        float cx = p2.x, cy = p2.y, zb = p2.z, zc = p2.w;

        // contracted reference edges: (qx-px)*(y-py) - (qy-py)*(x-px)
        float w0 = edge_fn(fs(cx, bxv), fs(y, byv), fs(cy, byv), fs(x, bxv));
        float w1 = edge_fn(fs(ax, cx),  fs(y, cy),  fs(ay, cy),  fs(x, cx));
        float w2 = edge_fn(fs(bxv, ax), fs(y, ay),  fs(byv, ay), fs(x, ax));

        // exact sign tests: sign(w/area) == sign(area<0 ? -w : w), incl. +-0
        bool neg = area < 0.0f;
        float t0 = neg ? -w0 : w0;
        float t1 = neg ? -w1 : w1;
        float t2 = neg ? -w2 : w2;
        bool inside = (t0 >= 0.0f) & (t1 >= 0.0f) & (t2 >= 0.0f);
        if (!__any_sync(0xffffffffu, inside)) continue;

        // cheap depth screen: |z_t - z| ~ few ulp once signs pass; margin 1e-4.
        bool cand = false;
        if (inside) {
            float z_t = ff3(fm(w2, ia), zc, ff3(fm(w0, ia), za, fm(fm(w1, ia), zb)));
            cand = (z_t >= -1.0001f) & (z_t <= 1.0001f) & (z_t < bd + 1e-4f);
        }
        if (__any_sync(0xffffffffu, cand)) {
            if (cand) {
                // exact path, bit-identical to reference
                float b0 = fd(w0, area);
                float b1 = fd(w1, area);
                float b2 = fd(w2, area);
                float z = ff3(b2, zc, ff3(b0, za, fm(b1, zb)));
                if (z >= -1.0f && z <= 1.0f && z < bd) { bd = z; bi = idx; }
            }
        }
    }

    if (bi != 0x7fffffff) {
        unsigned long long key =
            ((unsigned long long)zkey(bd) << 32) | (unsigned int)bi;
        atomicMin(&g_best[pid], key);           // (z asc, idx asc) == argmin
    }
}

// ======================= shade: 128 blocks x 128 =============================
__global__ void __launch_bounds__(128) shade_kernel(const int* __restrict__ f,
                                                    const float* __restrict__ vc,
                                                    const float* __restrict__ bg,
                                                    float* __restrict__ out) {
    int pid = blockIdx.x * 128 + threadIdx.x;
    unsigned long long key = g_best[pid];
    float r, g, b;
    if (key != EMPTY_KEY) {
        int bi = (int)(key & 0xFFFFFFFFu);
        float x = (float)(pid & (WIMG - 1)) + 0.5f;
        float y = (float)(pid >> 7) + 0.5f;
        float4 p0 = __ldg(&g_tri0[bi]);
        float4 p1 = __ldg(&g_tri1[bi]);
        float4 p2 = __ldg(&g_tri2[bi]);
        float area = p0.y;
        float ax = p1.x, ay = p1.y, bxv = p1.z, byv = p1.w;
        float cx = p2.x, cy = p2.y;
        // recompute winner barycentrics through the identical exact ops
        float w0 = edge_fn(fs(cx, bxv), fs(y, byv), fs(cy, byv), fs(x, bxv));
        float w1 = edge_fn(fs(ax, cx),  fs(y, cy),  fs(ay, cy),  fs(x, cx));
        float w2 = edge_fn(fs(bxv, ax), fs(y, ay),  fs(byv, ay), fs(x, ax));
        float b0 = fd(w0, area);
        float b1 = fd(w1, area);
        float b2 = fd(w2, area);
        int i0 = f[3 * bi], i1 = f[3 * bi + 1], i2 = f[3 * bi + 2];
        float k0 = fm(b0, g_iw[i0]);
        float k1 = fm(b1, g_iw[i1]);
        float k2 = fm(b2, g_iw[i2]);
        float den = fa(fa(k0, k1), k2);
        if (!(fabsf(den) > 1e-8f)) den = 1.0f;
        r = fd(ff3(k2, vc[3 * i2 + 0], ff3(k0, vc[3 * i0 + 0], fm(k1, vc[3 * i1 + 0]))), den);
        g = fd(ff3(k2, vc[3 * i2 + 1], ff3(k0, vc[3 * i0 + 1], fm(k1, vc[3 * i1 + 1]))), den);
        b = fd(ff3(k2, vc[3 * i2 + 2], ff3(k0, vc[3 * i0 + 2], fm(k1, vc[3 * i1 + 2]))), den);
    } else {
        r = bg[0]; g = bg[1]; b = bg[2];
    }
    out[pid * 3 + 0] = r;
    out[pid * 3 + 1] = g;
    out[pid * 3 + 2] = b;
}

extern "C" void kernel_launch(void* const* d_in, const int* in_sizes, int n_in,
                              void* d_out, int out_size) {
    const float* v   = (const float*)d_in[0];
    const float* vc  = (const float*)d_in[1];
    const int*   f   = (const int*)d_in[2];
    const float* bg  = (const float*)d_in[3];
    const float* cf  = (const float*)d_in[4];
    const float* cc  = (const float*)d_in[5];
    const float* ct  = (const float*)d_in[6];
    const float* crt = (const float*)d_in[7];

    setup_kernel<<<1, 512>>>(v, f, cf, cc, ct, crt);
    raster_kernel<<<NPIX / 32 * 2, 128>>>();
    shade_kernel<<<NPIX / 128, 128>>>(f, vc, bg, (float*)d_out);
}

// round 8
// speedup vs baseline: 1.6972x; 1.6972x over previous
#include <cuda_runtime.h>

#define WIMG 128
#define HIMG 128
#define NV   512
#define NF   1024
#define NPIX (WIMG * HIMG)

// ---- scratch (no allocations allowed) ----
__device__ float4 g_tri0[NF];   // (bbox_u32, area, inv_area, za)
__device__ float4 g_tri1[NF];   // (ax, ay, bx, by)
__device__ float4 g_tri2[NF];   // (cx, cy, zb, zc)
__device__ float  g_iw[NV];

__device__ __forceinline__ float fm(float a, float b) { return __fmul_rn(a, b); }
__device__ __forceinline__ float fa(float a, float b) { return __fadd_rn(a, b); }
__device__ __forceinline__ float fs(float a, float b) { return __fsub_rn(a, b); }
__device__ __forceinline__ float fd(float a, float b) { return __fdiv_rn(a, b); }
__device__ __forceinline__ float ff3(float a, float b, float c) { return __fmaf_rn(a, b, c); }

// XLA-contracted edge/area form: a*b - c*d  ->  fma(a, b, -(c*d))
__device__ __forceinline__ float edge_fn(float a, float b, float c, float d) {
    return ff3(a, b, -fm(c, d));
}

// ================= setup: one block, 512 threads =================
// Camera matrix computed by WARP 0 ONLY (MUFU cost scales with warps
// executing the divide chain), broadcast through smem.
__global__ void setup_kernel(const float* __restrict__ v,
                             const int* __restrict__ f,
                             const float* __restrict__ cf,
                             const float* __restrict__ cc,
                             const float* __restrict__ ct,
                             const float* __restrict__ crt) {
    __shared__ float sM[16];
    __shared__ float sxs[NV], sys[NV], szn[NV];
    int t = threadIdx.x;

    if (t < 32) {
        // ---- Rodrigues ----
        float rx = crt[0], ry = crt[1], rz = crt[2];
        float ssq = fa(fa(fm(rx, rx), fm(ry, ry)), fm(rz, rz));
        float theta = __fsqrt_rn(fa(ssq, 1e-12f));
        float kx = fd(rx, theta), ky = fd(ry, theta), kz = fd(rz, theta);
        float K[3][3] = {{0.f, -kz, ky}, {kz, 0.f, -kx}, {-ky, kx, 0.f}};
        float KK[3][3];
        #pragma unroll
        for (int i = 0; i < 3; i++)
            #pragma unroll
            for (int j = 0; j < 3; j++) {
                float s = fm(K[i][0], K[0][j]);
                s = ff3(K[i][1], K[1][j], s);
                s = ff3(K[i][2], K[2][j], s);
                KK[i][j] = s;
            }
        float sth = sinf(theta), cth1 = fs(1.0f, cosf(theta));
        float R[3][3];
        #pragma unroll
        for (int i = 0; i < 3; i++)
            #pragma unroll
            for (int j = 0; j < 3; j++) {
                float e = (i == j) ? 1.0f : 0.0f;
                R[i][j] = ff3(cth1, KK[i][j], ff3(sth, K[i][j], e));
            }
        float Mr[4][4] = {{0}}, Mt[4][4] = {{0}};
        #pragma unroll
        for (int i = 0; i < 4; i++) { Mr[i][i] = 1.f; Mt[i][i] = 1.f; }
        #pragma unroll
        for (int i = 0; i < 3; i++)
            #pragma unroll
            for (int j = 0; j < 3; j++) Mr[i][j] = R[j][i];
        Mt[3][0] = ct[0]; Mt[3][1] = ct[1]; Mt[3][2] = ct[2];
        float Vw[4][4];
        #pragma unroll
        for (int i = 0; i < 4; i++)
            #pragma unroll
            for (int j = 0; j < 4; j++) {
                float s = fm(Mr[i][0], Mt[0][j]);
                s = ff3(Mr[i][1], Mt[1][j], s);
                s = ff3(Mr[i][2], Mt[2][j], s);
                s = ff3(Mr[i][3], Mt[3][j], s);
                Vw[i][j] = s;
            }
        float ffv = fm(0.5f, fa(cf[0], cf[1]));
        float nf = fd(0.1f, ffv);
        float cx0 = fa(cc[0], 0.5f);
        float right  = fm(fs(128.0f, cx0), nf);
        float left   = -fm(cx0, nf);
        float top    = fm(fa(cc[1], 0.5f), nf);
        float bottom = -fm(fa(fs(128.0f, cc[1]), 0.5f), nf);
        float P[4][4] = {{0}};
        P[0][0] = fd(0.2f, fs(right, left));
        P[1][1] = fd(0.2f, fs(top, bottom));
        P[2][0] = fd(fa(right, left), fs(right, left));
        P[2][1] = fd(fa(top, bottom), fs(top, bottom));
        P[2][2] = (float)(-(10.0 + 0.1) / (10.0 - 0.1));
        P[2][3] = -1.0f;
        P[3][2] = (float)(-2.0 * 10.0 * 0.1 / (10.0 - 0.1));
        #pragma unroll
        for (int i = 0; i < 4; i++)
            #pragma unroll
            for (int j = 0; j < 4; j++) {
                float s = fm(Vw[i][0], P[0][j]);
                s = ff3(Vw[i][1], P[1][j], s);
                s = ff3(Vw[i][2], P[2][j], s);
                s = ff3(Vw[i][3], P[3][j], s);
                if (t == 0) sM[i * 4 + j] = s;
            }
    }
    __syncthreads();

    // ---- vertex transform (1 per thread) ----
    if (t < NV) {
        float vx = v[3 * t], vy = v[3 * t + 1], vz = v[3 * t + 2];
        float c[4];
        #pragma unroll
        for (int j = 0; j < 4; j++) {
            float s = fm(vx, sM[0 * 4 + j]);
            s = ff3(vy, sM[1 * 4 + j], s);
            s = ff3(vz, sM[2 * 4 + j], s);
            s = ff3(1.0f, sM[3 * 4 + j], s);
            c[j] = s;
        }
        int vld = (c[3] > 1e-8f) ? 1 : 0;
        float ws = vld ? c[3] : 1.0f;
        float nx = fd(c[0], ws), ny = fd(c[1], ws), nz = fd(c[2], ws);
        sxs[t] = fm(ff3(nx, 0.5f, 0.5f), 128.0f);   // pow2 scales: exact
        sys[t] = fm(fs(0.5f, fm(ny, 0.5f)), 128.0f);
        szn[t] = vld ? nz : __int_as_float(0x7FC00000);  // NaN marks invalid
        g_iw[t] = fd(1.0f, ws);
    }
    __syncthreads();

    // ---- triangle setup (2 per thread) ----
    for (int k = t; k < NF; k += 512) {
        int i0 = f[3 * k], i1 = f[3 * k + 1], i2 = f[3 * k + 2];
        float ax = sxs[i0], ay = sys[i0];
        float bx = sxs[i1], by = sys[i1];
        float cx = sxs[i2], cy = sys[i2];
        float area = edge_fn(fs(bx, ax), fs(cy, ay), fs(by, ay), fs(cx, ax));
        float za = szn[i0], zb = szn[i1], zc = szn[i2];
        bool zok = (za == za) && (zb == zb) && (zc == zc);
        bool ok = zok && (fabsf(area) > 1e-8f);
        float nanf = __int_as_float(0x7FC00000);
        float area_s = ok ? area : nanf;        // poisons exact path
        float ia     = ok ? fd(1.0f, area) : nanf;

        // conservative pixel-space bbox (u8x4); 255 in ixlo => always cull
        unsigned int packed = 255u;
        if (ok) {
            float xmin = fminf(ax, fminf(bx, cx));
            float xmax = fmaxf(ax, fmaxf(bx, cx));
            float ymin = fminf(ay, fminf(by, cy));
            float ymax = fmaxf(ay, fmaxf(by, cy));
            if (!(xmax < 0.5f || xmin > 127.5f || ymax < 0.5f || ymin > 127.5f)) {
                int ixlo = (int)floorf(fminf(fmaxf(xmin - 0.5f, 0.f), 127.f));
                int ixhi = (int)ceilf (fminf(fmaxf(xmax - 0.5f, 0.f), 127.f));
                int iylo = (int)floorf(fminf(fmaxf(ymin - 0.5f, 0.f), 127.f));
                int iyhi = (int)ceilf (fminf(fmaxf(ymax - 0.5f, 0.f), 127.f));
                packed = (unsigned)ixlo | ((unsigned)ixhi << 8) |
                         ((unsigned)iylo << 16) | ((unsigned)iyhi << 24);
            }
        }
        g_tri0[k] = make_float4(__uint_as_float(packed), area_s, ia, za);
        g_tri1[k] = make_float4(ax, ay, bx, by);
        g_tri2[k] = make_float4(cx, cy, zb, zc);
    }
}

// ================= raster: 512 blocks x 256 threads =================
// Block = 32-pixel strip; warp wi (0..7) handles triangles [wi*128, wi*128+128).
// Triangle index warp-uniform -> broadcast LDS. Merge 8 warps in smem.
extern "C" __global__ void __launch_bounds__(256, 4)
raster_kernel(const int* __restrict__ f,
              const float* __restrict__ vc,
              const float* __restrict__ bg,
              float* __restrict__ out) {
    extern __shared__ char smem[];
    float4* T0 = (float4*)(smem);
    float4* T1 = (float4*)(smem + 16384);
    float4* T2 = (float4*)(smem + 32768);
    int t = threadIdx.x;

    // stage all triangle records (48 KB)
    #pragma unroll
    for (int j = t; j < NF; j += 256) {
        T0[j] = g_tri0[j];
        T1[j] = g_tri1[j];
        T2[j] = g_tri2[j];
    }
    __syncthreads();

    int wi   = t >> 5;                          // triangle split 0..7
    int lane = t & 31;
    int pg   = blockIdx.x;
    int bx0  = 32 * (pg & 3);
    int iy   = pg >> 2;
    float x = (float)(bx0 + lane) + 0.5f;
    float y = (float)iy + 0.5f;

    float bd = __int_as_float(0x7f800000);      // +inf
    int   bi = 0x7fffffff;
    float bb0 = 0.f, bb1 = 0.f, bb2 = 0.f;

    int base = wi * (NF / 8);
    #pragma unroll 4
    for (int i = 0; i < NF / 8; ++i) {
        int idx = base + i;                     // warp-uniform
        float4 p0 = T0[idx];
        unsigned int bb = __float_as_uint(p0.x);
        int ixlo = bb & 255, ixhi = (bb >> 8) & 255;
        int iylo = (bb >> 16) & 255, iyhi = (bb >> 24) & 255;
        if (iyhi < iy || iylo > iy || ixhi < bx0 || ixlo > bx0 + 31) continue;

        float area = p0.y, ia = p0.z, za = p0.w;
        float4 p1 = T1[idx];
        float4 p2 = T2[idx];
        float ax = p1.x, ay = p1.y, bxv = p1.z, byv = p1.w;
        float cx = p2.x, cy = p2.y, zb = p2.z, zc = p2.w;

        // contracted reference edges: (qx-px)*(y-py) - (qy-py)*(x-px)
        float w0 = edge_fn(fs(cx, bxv), fs(y, byv), fs(cy, byv), fs(x, bxv));
        float w1 = edge_fn(fs(ax, cx),  fs(y, cy),  fs(ay, cy),  fs(x, cx));
        float w2 = edge_fn(fs(bxv, ax), fs(y, ay),  fs(byv, ay), fs(x, ax));

        // exact sign tests: sign(w/area) == sign(area<0 ? -w : w), incl. +-0
        bool neg = area < 0.0f;
        float t0 = neg ? -w0 : w0;
        float t1 = neg ? -w1 : w1;
        float t2 = neg ? -w2 : w2;
        bool inside = (t0 >= 0.0f) & (t1 >= 0.0f) & (t2 >= 0.0f);
        if (!__any_sync(0xffffffffu, inside)) continue;

        // cheap depth screen: |z_t - z| ~ few ulp once signs pass; margin 1e-4
        bool cand = false;
        if (inside) {
            float z_t = ff3(fm(w2, ia), zc, ff3(fm(w0, ia), za, fm(fm(w1, ia), zb)));
            cand = (z_t >= -1.0001f) & (z_t <= 1.0001f) & (z_t < bd + 1e-4f);
        }
        if (__any_sync(0xffffffffu, cand)) {
            if (cand) {
                // exact path, bit-identical to reference
                float b0 = fd(w0, area);
                float b1 = fd(w1, area);
                float b2 = fd(w2, area);
                float z = ff3(b2, zc, ff3(b0, za, fm(b1, zb)));
                if (z >= -1.0f && z <= 1.0f && z < bd) {
                    bd = z; bi = idx; bb0 = b0; bb1 = b1; bb2 = b2;
                }
            }
        }
    }

    // ---- merge 8 warps via smem (reuse T0 region after sync) ----
    __syncthreads();
    float* mz = (float*)smem;                   // [256]
    int*   mi = (int*)(smem + 1024);            // [256]
    float* m0 = (float*)(smem + 2048);          // [256]
    float* m1 = (float*)(smem + 3072);          // [256]
    float* m2 = (float*)(smem + 4096);          // [256]
    mz[t] = bd; mi[t] = bi; m0[t] = bb0; m1[t] = bb1; m2[t] = bb2;
    __syncthreads();

    if (t < 32) {
        #pragma unroll
        for (int w = 1; w < 8; ++w) {
            float zo = mz[w * 32 + t];
            int   io = mi[w * 32 + t];
            if (zo < bd || (zo == bd && io < bi)) {
                bd = zo; bi = io;
                bb0 = m0[w * 32 + t]; bb1 = m1[w * 32 + t]; bb2 = m2[w * 32 + t];
            }
        }

        float r, g, b;
        if (bd <= 1.0f) {
            int i0 = f[3 * bi], i1 = f[3 * bi + 1], i2 = f[3 * bi + 2];
            float k0 = fm(bb0, g_iw[i0]);
            float k1 = fm(bb1, g_iw[i1]);
            float k2 = fm(bb2, g_iw[i2]);
            float den = fa(fa(k0, k1), k2);
            if (!(fabsf(den) > 1e-8f)) den = 1.0f;
            r = fd(ff3(k2, vc[3 * i2 + 0], ff3(k0, vc[3 * i0 + 0], fm(k1, vc[3 * i1 + 0]))), den);
            g = fd(ff3(k2, vc[3 * i2 + 1], ff3(k0, vc[3 * i0 + 1], fm(k1, vc[3 * i1 + 1]))), den);
            b = fd(ff3(k2, vc[3 * i2 + 2], ff3(k0, vc[3 * i0 + 2], fm(k1, vc[3 * i1 + 2]))), den);
        } else {
            r = bg[0]; g = bg[1]; b = bg[2];
        }
        int p = pg * 32 + t;
        out[p * 3 + 0] = r;
        out[p * 3 + 1] = g;
        out[p * 3 + 2] = b;
    }
}

extern "C" void kernel_launch(void* const* d_in, const int* in_sizes, int n_in,
                              void* d_out, int out_size) {
    const float* v   = (const float*)d_in[0];
    const float* vc  = (const float*)d_in[1];
    const int*   f   = (const int*)d_in[2];
    const float* bg  = (const float*)d_in[3];
    const float* cf  = (const float*)d_in[4];
    const float* cc  = (const float*)d_in[5];
    const float* ct  = (const float*)d_in[6];
    const float* crt = (const float*)d_in[7];

    static int attr_done = 0;
    if (!attr_done) {
        cudaFuncSetAttribute(raster_kernel,
                             cudaFuncAttributeMaxDynamicSharedMemorySize,
                             49152);
        attr_done = 1;
    }
    setup_kernel<<<1, 512>>>(v, f, cf, cc, ct, crt);
    raster_kernel<<<NPIX / 32, 256, 49152>>>(f, vc, bg, (float*)d_out);
}

// round 9
// speedup vs baseline: 1.9044x; 1.1221x over previous
#include <cuda_runtime.h>

#define WIMG 128
#define HIMG 128
#define NV   512
#define NF   1024
#define NPIX (WIMG * HIMG)
#define RASTER_SMEM 53248   // 48K tri + 4K bbox + 1K pad

// ---- scratch (no allocations allowed) ----
__device__ float4 g_tri0[NF];        // (unused, area, inv_area, za)
__device__ float4 g_tri1[NF];        // (ax, ay, bx, by)
__device__ float4 g_tri2[NF];        // (cx, cy, zb, zc)
__device__ unsigned int g_bb[NF];    // packed bbox u8x4
__device__ float  g_iw[NV];

__device__ __forceinline__ float fm(float a, float b) { return __fmul_rn(a, b); }
__device__ __forceinline__ float fa(float a, float b) { return __fadd_rn(a, b); }
__device__ __forceinline__ float fs(float a, float b) { return __fsub_rn(a, b); }
__device__ __forceinline__ float fd(float a, float b) { return __fdiv_rn(a, b); }
__device__ __forceinline__ float ff3(float a, float b, float c) { return __fmaf_rn(a, b, c); }

// XLA-contracted edge/area form: a*b - c*d  ->  fma(a, b, -(c*d))
__device__ __forceinline__ float edge_fn(float a, float b, float c, float d) {
    return ff3(a, b, -fm(c, d));
}

// ================= setup: one block, 512 threads =================
// Camera matrix computed by WARP 0 ONLY (MUFU cost scales with warps
// executing the divide chain), broadcast through smem.
__global__ void setup_kernel(const float* __restrict__ v,
                             const int* __restrict__ f,
                             const float* __restrict__ cf,
                             const float* __restrict__ cc,
                             const float* __restrict__ ct,
                             const float* __restrict__ crt) {
    __shared__ float sM[16];
    __shared__ float sxs[NV], sys[NV], szn[NV];
    int t = threadIdx.x;

    if (t < 32) {
        // ---- Rodrigues ----
        float rx = crt[0], ry = crt[1], rz = crt[2];
        float ssq = fa(fa(fm(rx, rx), fm(ry, ry)), fm(rz, rz));
        float theta = __fsqrt_rn(fa(ssq, 1e-12f));
        float kx = fd(rx, theta), ky = fd(ry, theta), kz = fd(rz, theta);
        float K[3][3] = {{0.f, -kz, ky}, {kz, 0.f, -kx}, {-ky, kx, 0.f}};
        float KK[3][3];
        #pragma unroll
        for (int i = 0; i < 3; i++)
            #pragma unroll
            for (int j = 0; j < 3; j++) {
                float s = fm(K[i][0], K[0][j]);
                s = ff3(K[i][1], K[1][j], s);
                s = ff3(K[i][2], K[2][j], s);
                KK[i][j] = s;
            }
        float sth = sinf(theta), cth1 = fs(1.0f, cosf(theta));
        float R[3][3];
        #pragma unroll
        for (int i = 0; i < 3; i++)
            #pragma unroll
            for (int j = 0; j < 3; j++) {
                float e = (i == j) ? 1.0f : 0.0f;
                R[i][j] = ff3(cth1, KK[i][j], ff3(sth, K[i][j], e));
            }
        float Mr[4][4] = {{0}}, Mt[4][4] = {{0}};
        #pragma unroll
        for (int i = 0; i < 4; i++) { Mr[i][i] = 1.f; Mt[i][i] = 1.f; }
        #pragma unroll
        for (int i = 0; i < 3; i++)
            #pragma unroll
            for (int j = 0; j < 3; j++) Mr[i][j] = R[j][i];
        Mt[3][0] = ct[0]; Mt[3][1] = ct[1]; Mt[3][2] = ct[2];
        float Vw[4][4];
        #pragma unroll
        for (int i = 0; i < 4; i++)
            #pragma unroll
            for (int j = 0; j < 4; j++) {
                float s = fm(Mr[i][0], Mt[0][j]);
                s = ff3(Mr[i][1], Mt[1][j], s);
                s = ff3(Mr[i][2], Mt[2][j], s);
                s = ff3(Mr[i][3], Mt[3][j], s);
                Vw[i][j] = s;
            }
        float ffv = fm(0.5f, fa(cf[0], cf[1]));
        float nf = fd(0.1f, ffv);
        float cx0 = fa(cc[0], 0.5f);
        float right  = fm(fs(128.0f, cx0), nf);
        float left   = -fm(cx0, nf);
        float top    = fm(fa(cc[1], 0.5f), nf);
        float bottom = -fm(fa(fs(128.0f, cc[1]), 0.5f), nf);
        float P[4][4] = {{0}};
        P[0][0] = fd(0.2f, fs(right, left));
        P[1][1] = fd(0.2f, fs(top, bottom));
        P[2][0] = fd(fa(right, left), fs(right, left));
        P[2][1] = fd(fa(top, bottom), fs(top, bottom));
        P[2][2] = (float)(-(10.0 + 0.1) / (10.0 - 0.1));
        P[2][3] = -1.0f;
        P[3][2] = (float)(-2.0 * 10.0 * 0.1 / (10.0 - 0.1));
        #pragma unroll
        for (int i = 0; i < 4; i++)
            #pragma unroll
            for (int j = 0; j < 4; j++) {
                float s = fm(Vw[i][0], P[0][j]);
                s = ff3(Vw[i][1], P[1][j], s);
                s = ff3(Vw[i][2], P[2][j], s);
                s = ff3(Vw[i][3], P[3][j], s);
                if (t == 0) sM[i * 4 + j] = s;
            }
    }
    __syncthreads();

    // ---- vertex transform (1 per thread) ----
    if (t < NV) {
        float vx = v[3 * t], vy = v[3 * t + 1], vz = v[3 * t + 2];
        float c[4];
        #pragma unroll
        for (int j = 0; j < 4; j++) {
            float s = fm(vx, sM[0 * 4 + j]);
            s = ff3(vy, sM[1 * 4 + j], s);
            s = ff3(vz, sM[2 * 4 + j], s);
            s = ff3(1.0f, sM[3 * 4 + j], s);
            c[j] = s;
        }
        int vld = (c[3] > 1e-8f) ? 1 : 0;
        float ws = vld ? c[3] : 1.0f;
        float nx = fd(c[0], ws), ny = fd(c[1], ws), nz = fd(c[2], ws);
        sxs[t] = fm(ff3(nx, 0.5f, 0.5f), 128.0f);   // pow2 scales: exact
        sys[t] = fm(fs(0.5f, fm(ny, 0.5f)), 128.0f);
        szn[t] = vld ? nz : __int_as_float(0x7FC00000);  // NaN marks invalid
        g_iw[t] = fd(1.0f, ws);
    }
    __syncthreads();

    // ---- triangle setup (2 per thread) ----
    for (int k = t; k < NF; k += 512) {
        int i0 = f[3 * k], i1 = f[3 * k + 1], i2 = f[3 * k + 2];
        float ax = sxs[i0], ay = sys[i0];
        float bx = sxs[i1], by = sys[i1];
        float cx = sxs[i2], cy = sys[i2];
        float area = edge_fn(fs(bx, ax), fs(cy, ay), fs(by, ay), fs(cx, ax));
        float za = szn[i0], zb = szn[i1], zc = szn[i2];
        bool zok = (za == za) && (zb == zb) && (zc == zc);
        bool ok = zok && (fabsf(area) > 1e-8f);
        float nanf = __int_as_float(0x7FC00000);
        float area_s = ok ? area : nanf;        // poisons exact path
        float ia     = ok ? fd(1.0f, area) : nanf;

        // conservative pixel-space bbox (u8x4); lo>hi => always cull
        unsigned int packed = 0x000000FFu;      // ixlo=255 > ixhi=0
        if (ok) {
            float xmin = fminf(ax, fminf(bx, cx));
            float xmax = fmaxf(ax, fmaxf(bx, cx));
            float ymin = fminf(ay, fminf(by, cy));
            float ymax = fmaxf(ay, fmaxf(by, cy));
            if (!(xmax < 0.5f || xmin > 127.5f || ymax < 0.5f || ymin > 127.5f)) {
                int ixlo = (int)floorf(fminf(fmaxf(xmin - 0.5f, 0.f), 127.f));
                int ixhi = (int)ceilf (fminf(fmaxf(xmax - 0.5f, 0.f), 127.f));
                int iylo = (int)floorf(fminf(fmaxf(ymin - 0.5f, 0.f), 127.f));
                int iyhi = (int)ceilf (fminf(fmaxf(ymax - 0.5f, 0.f), 127.f));
                packed = (unsigned)ixlo | ((unsigned)ixhi << 8) |
                         ((unsigned)iylo << 16) | ((unsigned)iyhi << 24);
            }
        }
        g_bb[k]   = packed;
        g_tri0[k] = make_float4(0.f, area_s, ia, za);
        g_tri1[k] = make_float4(ax, ay, bx, by);
        g_tri2[k] = make_float4(cx, cy, zb, zc);
    }
}

// ================= raster: 512 blocks x 256 threads =================
// Block = 32-pixel strip; warp wi (0..7) owns triangles [wi*128, wi*128+128).
// Cull: 32 bboxes per ballot (1 per lane, coalesced LDS), then ffs-walk
// survivors with warp-uniform full evaluation (broadcast LDS).
extern "C" __global__ void __launch_bounds__(256, 4)
raster_kernel(const int* __restrict__ f,
              const float* __restrict__ vc,
              const float* __restrict__ bg,
              float* __restrict__ out) {
    extern __shared__ char smem[];
    float4*       T0  = (float4*)(smem);
    float4*       T1  = (float4*)(smem + 16384);
    float4*       T2  = (float4*)(smem + 32768);
    unsigned int* SBB = (unsigned int*)(smem + 49152);
    int t = threadIdx.x;

    #pragma unroll
    for (int j = t; j < NF; j += 256) {
        T0[j]  = g_tri0[j];
        T1[j]  = g_tri1[j];
        T2[j]  = g_tri2[j];
        SBB[j] = g_bb[j];
    }
    __syncthreads();

    int wi   = t >> 5;                          // triangle split 0..7
    int lane = t & 31;
    int pg   = blockIdx.x;
    int bx0  = 32 * (pg & 3);
    int iy   = pg >> 2;
    float x = (float)(bx0 + lane) + 0.5f;
    float y = (float)iy + 0.5f;

    float bd = __int_as_float(0x7f800000);      // +inf
    int   bi = 0x7fffffff;
    float bb0 = 0.f, bb1 = 0.f, bb2 = 0.f;

    int base = wi * (NF / 8);
    #pragma unroll
    for (int g = 0; g < (NF / 8) / 32; ++g) {   // 4 ballot groups of 32
        int tbase = base + g * 32;
        unsigned int bbv = SBB[tbase + lane];   // coalesced, conflict-free
        int ixlo = bbv & 255, ixhi = (bbv >> 8) & 255;
        int iylo = (bbv >> 16) & 255, iyhi = (bbv >> 24) & 255;
        bool pass = !(iyhi < iy || iylo > iy || ixhi < bx0 || ixlo > bx0 + 31);
        unsigned int mask = __ballot_sync(0xffffffffu, pass);

        while (mask) {
            int j = __ffs(mask) - 1;            // ascending idx: argmin order
            mask &= mask - 1;
            int idx = tbase + j;                // warp-uniform -> broadcast LDS

            float4 p0 = T0[idx];
            float area = p0.y, ia = p0.z, za = p0.w;
            float4 p1 = T1[idx];
            float4 p2 = T2[idx];
            float ax = p1.x, ay = p1.y, bxv = p1.z, byv = p1.w;
            float cx = p2.x, cy = p2.y, zb = p2.z, zc = p2.w;

            // contracted reference edges: (qx-px)*(y-py) - (qy-py)*(x-px)
            float w0 = edge_fn(fs(cx, bxv), fs(y, byv), fs(cy, byv), fs(x, bxv));
            float w1 = edge_fn(fs(ax, cx),  fs(y, cy),  fs(ay, cy),  fs(x, cx));
            float w2 = edge_fn(fs(bxv, ax), fs(y, ay),  fs(byv, ay), fs(x, ax));

            // exact sign tests: sign(w/area) == sign(area<0 ? -w : w), incl +-0
            bool neg = area < 0.0f;
            float t0 = neg ? -w0 : w0;
            float t1 = neg ? -w1 : w1;
            float t2 = neg ? -w2 : w2;
            bool inside = (t0 >= 0.0f) & (t1 >= 0.0f) & (t2 >= 0.0f);

            // cheap depth screen: |z_t - z| ~ few ulp once signs pass; 1e-4 margin
            bool cand = false;
            if (inside) {
                float z_t = ff3(fm(w2, ia), zc,
                                ff3(fm(w0, ia), za, fm(fm(w1, ia), zb)));
                cand = (z_t >= -1.0001f) & (z_t <= 1.0001f) & (z_t < bd + 1e-4f);
            }
            if (__any_sync(0xffffffffu, cand)) {
                if (cand) {
                    // exact path, bit-identical to reference
                    float b0 = fd(w0, area);
                    float b1 = fd(w1, area);
                    float b2 = fd(w2, area);
                    float z = ff3(b2, zc, ff3(b0, za, fm(b1, zb)));
                    if (z >= -1.0f && z <= 1.0f && z < bd) {
                        bd = z; bi = idx; bb0 = b0; bb1 = b1; bb2 = b2;
                    }
                }
            }
        }
    }

    // ---- merge 8 warps via smem (reuse T0 region after sync) ----
    __syncthreads();
    float* mz = (float*)smem;                   // [256]
    int*   mi = (int*)(smem + 1024);            // [256]
    float* m0 = (float*)(smem + 2048);          // [256]
    float* m1 = (float*)(smem + 3072);          // [256]
    float* m2 = (float*)(smem + 4096);          // [256]
    mz[t] = bd; mi[t] = bi; m0[t] = bb0; m1[t] = bb1; m2[t] = bb2;
    __syncthreads();

    if (t < 32) {
        #pragma unroll
        for (int w = 1; w < 8; ++w) {
            float zo = mz[w * 32 + t];
            int   io = mi[w * 32 + t];
            if (zo < bd || (zo == bd && io < bi)) {
                bd = zo; bi = io;
                bb0 = m0[w * 32 + t]; bb1 = m1[w * 32 + t]; bb2 = m2[w * 32 + t];
            }
        }

        float r, g, b;
        if (bd <= 1.0f) {
            int i0 = f[3 * bi], i1 = f[3 * bi + 1], i2 = f[3 * bi + 2];
            float k0 = fm(bb0, g_iw[i0]);
            float k1 = fm(bb1, g_iw[i1]);
            float k2 = fm(bb2, g_iw[i2]);
            float den = fa(fa(k0, k1), k2);
            if (!(fabsf(den) > 1e-8f)) den = 1.0f;
            r = fd(ff3(k2, vc[3 * i2 + 0], ff3(k0, vc[3 * i0 + 0], fm(k1, vc[3 * i1 + 0]))), den);
            g = fd(ff3(k2, vc[3 * i2 + 1], ff3(k0, vc[3 * i0 + 1], fm(k1, vc[3 * i1 + 1]))), den);
            b = fd(ff3(k2, vc[3 * i2 + 2], ff3(k0, vc[3 * i0 + 2], fm(k1, vc[3 * i1 + 2]))), den);
        } else {
            r = bg[0]; g = bg[1]; b = bg[2];
        }
        int p = pg * 32 + t;
        out[p * 3 + 0] = r;
        out[p * 3 + 1] = g;
        out[p * 3 + 2] = b;
    }
}

extern "C" void kernel_launch(void* const* d_in, const int* in_sizes, int n_in,
                              void* d_out, int out_size) {
    const float* v   = (const float*)d_in[0];
    const float* vc  = (const float*)d_in[1];
    const int*   f   = (const int*)d_in[2];
    const float* bg  = (const float*)d_in[3];
    const float* cf  = (const float*)d_in[4];
    const float* cc  = (const float*)d_in[5];
    const float* ct  = (const float*)d_in[6];
    const float* crt = (const float*)d_in[7];

    static int attr_done = 0;
    if (!attr_done) {
        cudaFuncSetAttribute(raster_kernel,
                             cudaFuncAttributeMaxDynamicSharedMemorySize,
                             RASTER_SMEM);
        attr_done = 1;
    }
    setup_kernel<<<1, 512>>>(v, f, cf, cc, ct, crt);
    raster_kernel<<<NPIX / 32, 256, RASTER_SMEM>>>(f, vc, bg, (float*)d_out);
}

// round 11
// speedup vs baseline: 2.1946x; 1.1524x over previous
#include <cuda_runtime.h>

#define WIMG 128
#define HIMG 128
#define NV   512
#define NF   1024
#define NPIX (WIMG * HIMG)
#define RASTER_SMEM 53248   // 48K tri + 4K bbox + 1K pad

// ---- scratch (no allocations allowed) ----
__device__ float4 g_tri0[NF];        // (unused, area, inv_area, za)
__device__ float4 g_tri1[NF];        // (ax, ay, bx, by)
__device__ float4 g_tri2[NF];        // (cx, cy, zb, zc)
__device__ unsigned int g_bb[NF];    // packed bbox u8x4
__device__ float  g_iw[NV];

__device__ __forceinline__ float fm(float a, float b) { return __fmul_rn(a, b); }
__device__ __forceinline__ float fa(float a, float b) { return __fadd_rn(a, b); }
__device__ __forceinline__ float fs(float a, float b) { return __fsub_rn(a, b); }
__device__ __forceinline__ float fd(float a, float b) { return __fdiv_rn(a, b); }
__device__ __forceinline__ float ff3(float a, float b, float c) { return __fmaf_rn(a, b, c); }

// XLA-contracted edge/area form: a*b - c*d  ->  fma(a, b, -(c*d))
__device__ __forceinline__ float edge_fn(float a, float b, float c, float d) {
    return ff3(a, b, -fm(c, d));
}

// ================= setup: one block, 512 threads =================
// Camera matrix computed by WARP 0 ONLY (MUFU cost scales with warps
// executing the divide chain), broadcast through smem.
__global__ void setup_kernel(const float* __restrict__ v,
                             const int* __restrict__ f,
                             const float* __restrict__ cf,
                             const float* __restrict__ cc,
                             const float* __restrict__ ct,
                             const float* __restrict__ crt) {
    __shared__ float sM[16];
    __shared__ float sxs[NV], sys[NV], szn[NV];
    int t = threadIdx.x;

    if (t < 32) {
        // ---- Rodrigues ----
        float rx = crt[0], ry = crt[1], rz = crt[2];
        float ssq = fa(fa(fm(rx, rx), fm(ry, ry)), fm(rz, rz));
        float theta = __fsqrt_rn(fa(ssq, 1e-12f));
        float kx = fd(rx, theta), ky = fd(ry, theta), kz = fd(rz, theta);
        float K[3][3] = {{0.f, -kz, ky}, {kz, 0.f, -kx}, {-ky, kx, 0.f}};
        float KK[3][3];
        #pragma unroll
        for (int i = 0; i < 3; i++)
            #pragma unroll
            for (int j = 0; j < 3; j++) {
                float s = fm(K[i][0], K[0][j]);
                s = ff3(K[i][1], K[1][j], s);
                s = ff3(K[i][2], K[2][j], s);
                KK[i][j] = s;
            }
        float sth = sinf(theta), cth1 = fs(1.0f, cosf(theta));
        float R[3][3];
        #pragma unroll
        for (int i = 0; i < 3; i++)
            #pragma unroll
            for (int j = 0; j < 3; j++) {
                float e = (i == j) ? 1.0f : 0.0f;
                R[i][j] = ff3(cth1, KK[i][j], ff3(sth, K[i][j], e));
            }
        float Mr[4][4] = {{0}}, Mt[4][4] = {{0}};
        #pragma unroll
        for (int i = 0; i < 4; i++) { Mr[i][i] = 1.f; Mt[i][i] = 1.f; }
        #pragma unroll
        for (int i = 0; i < 3; i++)
            #pragma unroll
            for (int j = 0; j < 3; j++) Mr[i][j] = R[j][i];
        Mt[3][0] = ct[0]; Mt[3][1] = ct[1]; Mt[3][2] = ct[2];
        float Vw[4][4];
        #pragma unroll
        for (int i = 0; i < 4; i++)
            #pragma unroll
            for (int j = 0; j < 4; j++) {
                float s = fm(Mr[i][0], Mt[0][j]);
                s = ff3(Mr[i][1], Mt[1][j], s);
                s = ff3(Mr[i][2], Mt[2][j], s);
                s = ff3(Mr[i][3], Mt[3][j], s);
                Vw[i][j] = s;
            }
        float ffv = fm(0.5f, fa(cf[0], cf[1]));
        float nf = fd(0.1f, ffv);
        float cx0 = fa(cc[0], 0.5f);
        float right  = fm(fs(128.0f, cx0), nf);
        float left   = -fm(cx0, nf);
        float top    = fm(fa(cc[1], 0.5f), nf);
        float bottom = -fm(fa(fs(128.0f, cc[1]), 0.5f), nf);
        float P[4][4] = {{0}};
        P[0][0] = fd(0.2f, fs(right, left));
        P[1][1] = fd(0.2f, fs(top, bottom));
        P[2][0] = fd(fa(right, left), fs(right, left));
        P[2][1] = fd(fa(top, bottom), fs(top, bottom));
        P[2][2] = (float)(-(10.0 + 0.1) / (10.0 - 0.1));
        P[2][3] = -1.0f;
        P[3][2] = (float)(-2.0 * 10.0 * 0.1 / (10.0 - 0.1));
        #pragma unroll
        for (int i = 0; i < 4; i++)
            #pragma unroll
            for (int j = 0; j < 4; j++) {
                float s = fm(Vw[i][0], P[0][j]);
                s = ff3(Vw[i][1], P[1][j], s);
                s = ff3(Vw[i][2], P[2][j], s);
                s = ff3(Vw[i][3], P[3][j], s);
                if (t == 0) sM[i * 4 + j] = s;
            }
    }
    __syncthreads();

    // ---- vertex transform (1 per thread) ----
    if (t < NV) {
        float vx = v[3 * t], vy = v[3 * t + 1], vz = v[3 * t + 2];
        float c[4];
        #pragma unroll
        for (int j = 0; j < 4; j++) {
            float s = fm(vx, sM[0 * 4 + j]);
            s = ff3(vy, sM[1 * 4 + j], s);
            s = ff3(vz, sM[2 * 4 + j], s);
            s = ff3(1.0f, sM[3 * 4 + j], s);
            c[j] = s;
        }
        int vld = (c[3] > 1e-8f) ? 1 : 0;
        float ws = vld ? c[3] : 1.0f;
        float nx = fd(c[0], ws), ny = fd(c[1], ws), nz = fd(c[2], ws);
        sxs[t] = fm(ff3(nx, 0.5f, 0.5f), 128.0f);   // pow2 scales: exact
        sys[t] = fm(fs(0.5f, fm(ny, 0.5f)), 128.0f);
        szn[t] = vld ? nz : __int_as_float(0x7FC00000);  // NaN marks invalid
        g_iw[t] = fd(1.0f, ws);
    }
    __syncthreads();

    // ---- triangle setup (2 per thread) ----
    for (int k = t; k < NF; k += 512) {
        int i0 = f[3 * k], i1 = f[3 * k + 1], i2 = f[3 * k + 2];
        float ax = sxs[i0], ay = sys[i0];
        float bx = sxs[i1], by = sys[i1];
        float cx = sxs[i2], cy = sys[i2];
        float area = edge_fn(fs(bx, ax), fs(cy, ay), fs(by, ay), fs(cx, ax));
        float za = szn[i0], zb = szn[i1], zc = szn[i2];
        bool zok = (za == za) && (zb == zb) && (zc == zc);
        bool ok = zok && (fabsf(area) > 1e-8f);
        float nanf = __int_as_float(0x7FC00000);
        float area_s = ok ? area : nanf;        // poisons exact path
        float ia     = ok ? fd(1.0f, area) : nanf;

        // conservative pixel-space bbox (u8x4); lo>hi => always cull
        unsigned int packed = 0x000000FFu;      // ixlo=255 > ixhi=0
        if (ok) {
            float xmin = fminf(ax, fminf(bx, cx));
            float xmax = fmaxf(ax, fmaxf(bx, cx));
            float ymin = fminf(ay, fminf(by, cy));
            float ymax = fmaxf(ay, fmaxf(by, cy));
            if (!(xmax < 0.5f || xmin > 127.5f || ymax < 0.5f || ymin > 127.5f)) {
                int ixlo = (int)floorf(fminf(fmaxf(xmin - 0.5f, 0.f), 127.f));
                int ixhi = (int)ceilf (fminf(fmaxf(xmax - 0.5f, 0.f), 127.f));
                int iylo = (int)floorf(fminf(fmaxf(ymin - 0.5f, 0.f), 127.f));
                int iyhi = (int)ceilf (fminf(fmaxf(ymax - 0.5f, 0.f), 127.f));
                packed = (unsigned)ixlo | ((unsigned)ixhi << 8) |
                         ((unsigned)iylo << 16) | ((unsigned)iyhi << 24);
            }
        }
        g_bb[k]   = packed;
        g_tri0[k] = make_float4(0.f, area_s, ia, za);
        g_tri1[k] = make_float4(ax, ay, bx, by);
        g_tri2[k] = make_float4(cx, cy, zb, zc);
    }
}

// ================= raster: 512 blocks x 256 threads =================
// Block = 8x4 pixel tile (smaller bbox-overlap cross-section than 32x1);
// warp wi (0..7) owns triangles [wi*128, wi*128+128).
// Cull: 32 bboxes per ballot (1 per lane, coalesced LDS), then ffs-walk
// survivors with warp-uniform full evaluation (broadcast LDS).
extern "C" __global__ void __launch_bounds__(256, 4)
raster_kernel(const int* __restrict__ f,
              const float* __restrict__ vc,
              const float* __restrict__ bg,
              float* __restrict__ out) {
    extern __shared__ char smem[];
    float4*       T0  = (float4*)(smem);
    float4*       T1  = (float4*)(smem + 16384);
    float4*       T2  = (float4*)(smem + 32768);
    unsigned int* SBB = (unsigned int*)(smem + 49152);
    int t = threadIdx.x;

    #pragma unroll
    for (int j = t; j < NF; j += 256) {
        T0[j]  = g_tri0[j];
        T1[j]  = g_tri1[j];
        T2[j]  = g_tri2[j];
        SBB[j] = g_bb[j];
    }
    __syncthreads();

    int wi   = t >> 5;                          // triangle split 0..7
    int lane = t & 31;
    int pg   = blockIdx.x;                      // tile id: 16 x-tiles, 32 y-tiles
    int tx0  = (pg & 15) * 8;
    int ty0  = (pg >> 4) * 4;
    int px   = tx0 + (lane & 7);
    int py   = ty0 + (lane >> 3);
    float x = (float)px + 0.5f;
    float y = (float)py + 0.5f;

    float bd = __int_as_float(0x7f800000);      // +inf
    int   bi = 0x7fffffff;
    float bb0 = 0.f, bb1 = 0.f, bb2 = 0.f;

    int base = wi * (NF / 8);
    #pragma unroll
    for (int g = 0; g < (NF / 8) / 32; ++g) {   // 4 ballot groups of 32
        int tbase = base + g * 32;
        unsigned int bbv = SBB[tbase + lane];   // coalesced, conflict-free
        int ixlo = bbv & 255, ixhi = (bbv >> 8) & 255;
        int iylo = (bbv >> 16) & 255, iyhi = (bbv >> 24) & 255;
        bool pass = !(iyhi < ty0 || iylo > ty0 + 3 || ixhi < tx0 || ixlo > tx0 + 7);
        unsigned int mask = __ballot_sync(0xffffffffu, pass);

        while (mask) {
            int j = __ffs(mask) - 1;            // ascending idx: argmin order
            mask &= mask - 1;
            int idx = tbase + j;                // warp-uniform -> broadcast LDS

            float4 p0 = T0[idx];
            float area = p0.y, ia = p0.z, za = p0.w;
            float4 p1 = T1[idx];
            float4 p2 = T2[idx];
            float ax = p1.x, ay = p1.y, bxv = p1.z, byv = p1.w;
            float cx = p2.x, cy = p2.y, zb = p2.z, zc = p2.w;

            // contracted reference edges: (qx-px)*(y-py) - (qy-py)*(x-px)
            float w0 = edge_fn(fs(cx, bxv), fs(y, byv), fs(cy, byv), fs(x, bxv));
            float w1 = edge_fn(fs(ax, cx),  fs(y, cy),  fs(ay, cy),  fs(x, cx));
            float w2 = edge_fn(fs(bxv, ax), fs(y, ay),  fs(byv, ay), fs(x, ax));

            // exact sign tests: sign(w/area) == sign(area<0 ? -w : w), incl +-0
            bool neg = area < 0.0f;
            float t0 = neg ? -w0 : w0;
            float t1 = neg ? -w1 : w1;
            float t2 = neg ? -w2 : w2;
            bool inside = (t0 >= 0.0f) & (t1 >= 0.0f) & (t2 >= 0.0f);

            // cheap depth screen: |z_t - z| ~ few ulp once signs pass; 1e-4 margin
            bool cand = false;
            if (inside) {
                float z_t = ff3(fm(w2, ia), zc,
                                ff3(fm(w0, ia), za, fm(fm(w1, ia), zb)));
                cand = (z_t >= -1.0001f) & (z_t <= 1.0001f) & (z_t < bd + 1e-4f);
            }
            if (__any_sync(0xffffffffu, cand)) {
                if (cand) {
                    // exact path, bit-identical to reference
                    float b0 = fd(w0, area);
                    float b1 = fd(w1, area);
                    float b2 = fd(w2, area);
                    float z = ff3(b2, zc, ff3(b0, za, fm(b1, zb)));
                    if (z >= -1.0f && z <= 1.0f && z < bd) {
                        bd = z; bi = idx; bb0 = b0; bb1 = b1; bb2 = b2;
                    }
                }
            }
        }
    }

    // ---- merge 8 warps via smem (reuse T0 region after sync) ----
    __syncthreads();
    float* mz = (float*)smem;                   // [256]
    int*   mi = (int*)(smem + 1024);            // [256]
    float* m0 = (float*)(smem + 2048);          // [256]
    float* m1 = (float*)(smem + 3072);          // [256]
    float* m2 = (float*)(smem + 4096);          // [256]
    mz[t] = bd; mi[t] = bi; m0[t] = bb0; m1[t] = bb1; m2[t] = bb2;
    __syncthreads();

    if (t < 32) {
        #pragma unroll
        for (int w = 1; w < 8; ++w) {
            float zo = mz[w * 32 + t];
            int   io = mi[w * 32 + t];
            if (zo < bd || (zo == bd && io < bi)) {
                bd = zo; bi = io;
                bb0 = m0[w * 32 + t]; bb1 = m1[w * 32 + t]; bb2 = m2[w * 32 + t];
            }
        }

        float r, g, b;
        if (bd <= 1.0f) {
            int i0 = f[3 * bi], i1 = f[3 * bi + 1], i2 = f[3 * bi + 2];
            float k0 = fm(bb0, g_iw[i0]);
            float k1 = fm(bb1, g_iw[i1]);
            float k2 = fm(bb2, g_iw[i2]);
            float den = fa(fa(k0, k1), k2);
            if (!(fabsf(den) > 1e-8f)) den = 1.0f;
            r = fd(ff3(k2, vc[3 * i2 + 0], ff3(k0, vc[3 * i0 + 0], fm(k1, vc[3 * i1 + 0]))), den);
            g = fd(ff3(k2, vc[3 * i2 + 1], ff3(k0, vc[3 * i0 + 1], fm(k1, vc[3 * i1 + 1]))), den);
            b = fd(ff3(k2, vc[3 * i2 + 2], ff3(k0, vc[3 * i0 + 2], fm(k1, vc[3 * i1 + 2]))), den);
        } else {
            r = bg[0]; g = bg[1]; b = bg[2];
        }
        int p = (ty0 + (t >> 3)) * WIMG + tx0 + (t & 7);
        out[p * 3 + 0] = r;
        out[p * 3 + 1] = g;
        out[p * 3 + 2] = b;
    }
}

extern "C" void kernel_launch(void* const* d_in, const int* in_sizes, int n_in,
                              void* d_out, int out_size) {
    const float* v   = (const float*)d_in[0];
    const float* vc  = (const float*)d_in[1];
    const int*   f   = (const int*)d_in[2];
    const float* bg  = (const float*)d_in[3];
    const float* cf  = (const float*)d_in[4];
    const float* cc  = (const float*)d_in[5];
    const float* ct  = (const float*)d_in[6];
    const float* crt = (const float*)d_in[7];

    static int attr_done = 0;
    if (!attr_done) {
        cudaFuncSetAttribute(raster_kernel,
                             cudaFuncAttributeMaxDynamicSharedMemorySize,
                             RASTER_SMEM);
        attr_done = 1;
    }
    setup_kernel<<<1, 512>>>(v, f, cf, cc, ct, crt);
    raster_kernel<<<NPIX / 32, 256, RASTER_SMEM>>>(f, vc, bg, (float*)d_out);
}

// round 12
// speedup vs baseline: 2.3696x; 1.0797x over previous
#include <cuda_runtime.h>

#define WIMG 128
#define HIMG 128
#define NV   512
#define NF   1024
#define NPIX (WIMG * HIMG)
#define RASTER_SMEM 53248   // 48K tri + 4K bbox + 1K pad

// ---- scratch (no allocations allowed) ----
__device__ float4 g_tri0[NF];        // (signmask, area, inv_area, za)
__device__ float4 g_tri1[NF];        // (ax, ay, bx, by)
__device__ float4 g_tri2[NF];        // (cx, cy, zb, zc)
__device__ unsigned int g_bb[NF];    // packed bbox u8x4
__device__ float  g_iw[NV];

__device__ __forceinline__ float fm(float a, float b) { return __fmul_rn(a, b); }
__device__ __forceinline__ float fa(float a, float b) { return __fadd_rn(a, b); }
__device__ __forceinline__ float fs(float a, float b) { return __fsub_rn(a, b); }
__device__ __forceinline__ float fd(float a, float b) { return __fdiv_rn(a, b); }
__device__ __forceinline__ float ff3(float a, float b, float c) { return __fmaf_rn(a, b, c); }

// XLA-contracted edge/area form: a*b - c*d  ->  fma(a, b, -(c*d))
__device__ __forceinline__ float edge_fn(float a, float b, float c, float d) {
    return ff3(a, b, -fm(c, d));
}

// ================= setup: one block, 512 threads =================
__global__ void setup_kernel(const float* __restrict__ v,
                             const int* __restrict__ f,
                             const float* __restrict__ cf,
                             const float* __restrict__ cc,
                             const float* __restrict__ ct,
                             const float* __restrict__ crt) {
    __shared__ float sM[16];
    __shared__ float sxs[NV], sys[NV], szn[NV];
    int t = threadIdx.x;

    if (t < 32) {
        // ---- Rodrigues ----
        float rx = crt[0], ry = crt[1], rz = crt[2];
        float ssq = fa(fa(fm(rx, rx), fm(ry, ry)), fm(rz, rz));
        float theta = __fsqrt_rn(fa(ssq, 1e-12f));
        float kx = fd(rx, theta), ky = fd(ry, theta), kz = fd(rz, theta);
        float K[3][3] = {{0.f, -kz, ky}, {kz, 0.f, -kx}, {-ky, kx, 0.f}};
        float KK[3][3];
        #pragma unroll
        for (int i = 0; i < 3; i++)
            #pragma unroll
            for (int j = 0; j < 3; j++) {
                float s = fm(K[i][0], K[0][j]);
                s = ff3(K[i][1], K[1][j], s);
                s = ff3(K[i][2], K[2][j], s);
                KK[i][j] = s;
            }
        float sth = sinf(theta), cth1 = fs(1.0f, cosf(theta));
        float R[3][3];
        #pragma unroll
        for (int i = 0; i < 3; i++)
            #pragma unroll
            for (int j = 0; j < 3; j++) {
                float e = (i == j) ? 1.0f : 0.0f;
                R[i][j] = ff3(cth1, KK[i][j], ff3(sth, K[i][j], e));
            }
        float Mr[4][4] = {{0}}, Mt[4][4] = {{0}};
        #pragma unroll
        for (int i = 0; i < 4; i++) { Mr[i][i] = 1.f; Mt[i][i] = 1.f; }
        #pragma unroll
        for (int i = 0; i < 3; i++)
            #pragma unroll
            for (int j = 0; j < 3; j++) Mr[i][j] = R[j][i];
        Mt[3][0] = ct[0]; Mt[3][1] = ct[1]; Mt[3][2] = ct[2];
        float Vw[4][4];
        #pragma unroll
        for (int i = 0; i < 4; i++)
            #pragma unroll
            for (int j = 0; j < 4; j++) {
                float s = fm(Mr[i][0], Mt[0][j]);
                s = ff3(Mr[i][1], Mt[1][j], s);
                s = ff3(Mr[i][2], Mt[2][j], s);
                s = ff3(Mr[i][3], Mt[3][j], s);
                Vw[i][j] = s;
            }
        float ffv = fm(0.5f, fa(cf[0], cf[1]));
        float nf = fd(0.1f, ffv);
        float cx0 = fa(cc[0], 0.5f);
        float right  = fm(fs(128.0f, cx0), nf);
        float left   = -fm(cx0, nf);
        float top    = fm(fa(cc[1], 0.5f), nf);
        float bottom = -fm(fa(fs(128.0f, cc[1]), 0.5f), nf);
        float P[4][4] = {{0}};
        P[0][0] = fd(0.2f, fs(right, left));
        P[1][1] = fd(0.2f, fs(top, bottom));
        P[2][0] = fd(fa(right, left), fs(right, left));
        P[2][1] = fd(fa(top, bottom), fs(top, bottom));
        P[2][2] = (float)(-(10.0 + 0.1) / (10.0 - 0.1));
        P[2][3] = -1.0f;
        P[3][2] = (float)(-2.0 * 10.0 * 0.1 / (10.0 - 0.1));
        #pragma unroll
        for (int i = 0; i < 4; i++)
            #pragma unroll
            for (int j = 0; j < 4; j++) {
                float s = fm(Vw[i][0], P[0][j]);
                s = ff3(Vw[i][1], P[1][j], s);
                s = ff3(Vw[i][2], P[2][j], s);
                s = ff3(Vw[i][3], P[3][j], s);
                if (t == 0) sM[i * 4 + j] = s;
            }
    }
    __syncthreads();

    // ---- vertex transform (1 per thread) ----
    if (t < NV) {
        float vx = v[3 * t], vy = v[3 * t + 1], vz = v[3 * t + 2];
        float c[4];
        #pragma unroll
        for (int j = 0; j < 4; j++) {
            float s = fm(vx, sM[0 * 4 + j]);
            s = ff3(vy, sM[1 * 4 + j], s);
            s = ff3(vz, sM[2 * 4 + j], s);
            s = ff3(1.0f, sM[3 * 4 + j], s);
            c[j] = s;
        }
        int vld = (c[3] > 1e-8f) ? 1 : 0;
        float ws = vld ? c[3] : 1.0f;
        float nx = fd(c[0], ws), ny = fd(c[1], ws), nz = fd(c[2], ws);
        sxs[t] = fm(ff3(nx, 0.5f, 0.5f), 128.0f);   // pow2 scales: exact
        sys[t] = fm(fs(0.5f, fm(ny, 0.5f)), 128.0f);
        szn[t] = vld ? nz : __int_as_float(0x7FC00000);  // NaN marks invalid
        g_iw[t] = fd(1.0f, ws);
    }
    __syncthreads();

    // ---- triangle setup (2 per thread) ----
    for (int k = t; k < NF; k += 512) {
        int i0 = f[3 * k], i1 = f[3 * k + 1], i2 = f[3 * k + 2];
        float ax = sxs[i0], ay = sys[i0];
        float bx = sxs[i1], by = sys[i1];
        float cx = sxs[i2], cy = sys[i2];
        float area = edge_fn(fs(bx, ax), fs(cy, ay), fs(by, ay), fs(cx, ax));
        float za = szn[i0], zb = szn[i1], zc = szn[i2];
        bool zok = (za == za) && (zb == zb) && (zc == zc);
        bool ok = zok && (fabsf(area) > 1e-8f);
        float nanf = __int_as_float(0x7FC00000);
        float area_s = ok ? area : nanf;        // poisons exact path
        float ia     = ok ? fd(1.0f, area) : nanf;
        // sign mask: XOR with w flips sign iff area < 0 (invalid tris culled)
        unsigned int sgn = (ok && area < 0.0f) ? 0x80000000u : 0u;

        // conservative pixel-space bbox (u8x4); lo>hi => always cull
        unsigned int packed = 0x000000FFu;      // ixlo=255 > ixhi=0
        if (ok) {
            float xmin = fminf(ax, fminf(bx, cx));
            float xmax = fmaxf(ax, fmaxf(bx, cx));
            float ymin = fminf(ay, fminf(by, cy));
            float ymax = fmaxf(ay, fmaxf(by, cy));
            if (!(xmax < 0.5f || xmin > 127.5f || ymax < 0.5f || ymin > 127.5f)) {
                int ixlo = (int)floorf(fminf(fmaxf(xmin - 0.5f, 0.f), 127.f));
                int ixhi = (int)ceilf (fminf(fmaxf(xmax - 0.5f, 0.f), 127.f));
                int iylo = (int)floorf(fminf(fmaxf(ymin - 0.5f, 0.f), 127.f));
                int iyhi = (int)ceilf (fminf(fmaxf(ymax - 0.5f, 0.f), 127.f));
                packed = (unsigned)ixlo | ((unsigned)ixhi << 8) |
                         ((unsigned)iylo << 16) | ((unsigned)iyhi << 24);
            }
        }
        g_bb[k]   = packed;
        g_tri0[k] = make_float4(__uint_as_float(sgn), area_s, ia, za);
        g_tri1[k] = make_float4(ax, ay, bx, by);
        g_tri2[k] = make_float4(cx, cy, zb, zc);
    }
}

// evaluate one triangle up to the candidate screen (no divides)
__device__ __forceinline__ void eval_tri(
    const float4* __restrict__ T0, const float4* __restrict__ T1,
    const float4* __restrict__ T2, int idx, float x, float y, float bd,
    bool& cand, float& w0, float& w1, float& w2,
    float& area, float& za, float& zb, float& zc)
{
    float4 p0 = T0[idx];
    unsigned int sgn = __float_as_uint(p0.x);
    area = p0.y; float ia = p0.z; za = p0.w;
    float4 p1 = T1[idx];
    float4 p2 = T2[idx];
    float ax = p1.x, ay = p1.y, bxv = p1.z, byv = p1.w;
    float cx = p2.x, cy = p2.y; zb = p2.z; zc = p2.w;

    // contracted reference edges: (qx-px)*(y-py) - (qy-py)*(x-px)
    w0 = edge_fn(fs(cx, bxv), fs(y, byv), fs(cy, byv), fs(x, bxv));
    w1 = edge_fn(fs(ax, cx),  fs(y, cy),  fs(ay, cy),  fs(x, cx));
    w2 = edge_fn(fs(bxv, ax), fs(y, ay),  fs(byv, ay), fs(x, ax));

    // exact sign tests: sign(w/area) == sign(sgn-flipped w), incl. +-0
    float t0 = __uint_as_float(__float_as_uint(w0) ^ sgn);
    float t1 = __uint_as_float(__float_as_uint(w1) ^ sgn);
    float t2 = __uint_as_float(__float_as_uint(w2) ^ sgn);
    bool inside = (t0 >= 0.0f) & (t1 >= 0.0f) & (t2 >= 0.0f);

    // cheap depth screen (conservative filter; exact path re-verifies)
    cand = false;
    if (inside) {
        float zs  = ff3(w2, zc, ff3(w0, za, fm(w1, zb)));
        float z_t = fm(zs, ia);                 // NaN ia -> cand false
        cand = (z_t >= -1.0001f) & (z_t <= 1.0001f) & (z_t < bd + 1e-4f);
    }
}

// ================= raster: 512 blocks x 256 threads =================
// Block = 8x4 pixel tile; warp wi (0..7) owns triangles [wi*128, wi*128+128).
// Ballot cull (32 bboxes/round), then pairwise survivor evaluation for ILP.
extern "C" __global__ void __launch_bounds__(256, 3)
raster_kernel(const int* __restrict__ f,
              const float* __restrict__ vc,
              const float* __restrict__ bg,
              float* __restrict__ out) {
    extern __shared__ char smem[];
    float4*       T0  = (float4*)(smem);
    float4*       T1  = (float4*)(smem + 16384);
    float4*       T2  = (float4*)(smem + 32768);
    unsigned int* SBB = (unsigned int*)(smem + 49152);
    int t = threadIdx.x;

    #pragma unroll
    for (int j = t; j < NF; j += 256) {
        T0[j]  = g_tri0[j];
        T1[j]  = g_tri1[j];
        T2[j]  = g_tri2[j];
        SBB[j] = g_bb[j];
    }
    __syncthreads();

    int wi   = t >> 5;                          // triangle split 0..7
    int lane = t & 31;
    int pg   = blockIdx.x;                      // tile id: 16 x-tiles, 32 y-tiles
    int tx0  = (pg & 15) * 8;
    int ty0  = (pg >> 4) * 4;
    float x = (float)(tx0 + (lane & 7)) + 0.5f;
    float y = (float)(ty0 + (lane >> 3)) + 0.5f;

    float bd = __int_as_float(0x7f800000);      // +inf
    int   bi = 0x7fffffff;
    float bb0 = 0.f, bb1 = 0.f, bb2 = 0.f;

    int base = wi * (NF / 8);
    #pragma unroll
    for (int g = 0; g < (NF / 8) / 32; ++g) {   // 4 ballot groups of 32
        int tbase = base + g * 32;
        unsigned int bbv = SBB[tbase + lane];   // coalesced, conflict-free
        int ixlo = bbv & 255, ixhi = (bbv >> 8) & 255;
        int iylo = (bbv >> 16) & 255, iyhi = (bbv >> 24) & 255;
        bool pass = !(iyhi < ty0 || iylo > ty0 + 3 || ixhi < tx0 || ixlo > tx0 + 7);
        unsigned int mask = __ballot_sync(0xffffffffu, pass);

        while (mask) {
            int idx1 = tbase + (__ffs(mask) - 1);
            mask &= mask - 1;
            bool has2 = (mask != 0);
            int idx2 = idx1;
            if (has2) { idx2 = tbase + (__ffs(mask) - 1); mask &= mask - 1; }

            // two independent eval chains: loads + math interleave (ILP)
            bool c1, c2;
            float aw0, aw1, aw2, aar, aza, azb, azc;
            float bw0, bw1, bw2, bar, bza, bzb, bzc;
            eval_tri(T0, T1, T2, idx1, x, y, bd, c1, aw0, aw1, aw2, aar, aza, azb, azc);
            eval_tri(T0, T1, T2, idx2, x, y, bd, c2, bw0, bw1, bw2, bar, bza, bzb, bzc);
            c2 = c2 && has2;

            if (__any_sync(0xffffffffu, c1 | c2)) {
                if (c1) {                        // exact path, bit-identical
                    float b0 = fd(aw0, aar);
                    float b1 = fd(aw1, aar);
                    float b2 = fd(aw2, aar);
                    float z = ff3(b2, azc, ff3(b0, aza, fm(b1, azb)));
                    if (z >= -1.0f && z <= 1.0f && z < bd) {
                        bd = z; bi = idx1; bb0 = b0; bb1 = b1; bb2 = b2;
                    }
                }
                if (c2) {                        // idx2 > idx1: order preserved
                    float b0 = fd(bw0, bar);
                    float b1 = fd(bw1, bar);
                    float b2 = fd(bw2, bar);
                    float z = ff3(b2, bzc, ff3(b0, bza, fm(b1, bzb)));
                    if (z >= -1.0f && z <= 1.0f && z < bd) {
                        bd = z; bi = idx2; bb0 = b0; bb1 = b1; bb2 = b2;
                    }
                }
            }
        }
    }

    // ---- merge 8 warps via smem (reuse T0 region after sync) ----
    __syncthreads();
    float* mz = (float*)smem;                   // [256]
    int*   mi = (int*)(smem + 1024);            // [256]
    float* m0 = (float*)(smem + 2048);          // [256]
    float* m1 = (float*)(smem + 3072);          // [256]
    float* m2 = (float*)(smem + 4096);          // [256]
    mz[t] = bd; mi[t] = bi; m0[t] = bb0; m1[t] = bb1; m2[t] = bb2;
    __syncthreads();

    if (t < 32) {
        #pragma unroll
        for (int w = 1; w < 8; ++w) {
            float zo = mz[w * 32 + t];
            int   io = mi[w * 32 + t];
            if (zo < bd || (zo == bd && io < bi)) {
                bd = zo; bi = io;
                bb0 = m0[w * 32 + t]; bb1 = m1[w * 32 + t]; bb2 = m2[w * 32 + t];
            }
        }

        float r, g, b;
        if (bd <= 1.0f) {
            int i0 = f[3 * bi], i1 = f[3 * bi + 1], i2 = f[3 * bi + 2];
            float k0 = fm(bb0, g_iw[i0]);
            float k1 = fm(bb1, g_iw[i1]);
            float k2 = fm(bb2, g_iw[i2]);
            float den = fa(fa(k0, k1), k2);
            if (!(fabsf(den) > 1e-8f)) den = 1.0f;
            r = fd(ff3(k2, vc[3 * i2 + 0], ff3(k0, vc[3 * i0 + 0], fm(k1, vc[3 * i1 + 0]))), den);
            g = fd(ff3(k2, vc[3 * i2 + 1], ff3(k0, vc[3 * i0 + 1], fm(k1, vc[3 * i1 + 1]))), den);
            b = fd(ff3(k2, vc[3 * i2 + 2], ff3(k0, vc[3 * i0 + 2], fm(k1, vc[3 * i1 + 2]))), den);
        } else {
            r = bg[0]; g = bg[1]; b = bg[2];
        }
        int p = (ty0 + (t >> 3)) * WIMG + tx0 + (t & 7);
        out[p * 3 + 0] = r;
        out[p * 3 + 1] = g;
        out[p * 3 + 2] = b;
    }
}

extern "C" void kernel_launch(void* const* d_in, const int* in_sizes, int n_in,
                              void* d_out, int out_size) {
    const float* v   = (const float*)d_in[0];
    const float* vc  = (const float*)d_in[1];
    const int*   f   = (const int*)d_in[2];
    const float* bg  = (const float*)d_in[3];
    const float* cf  = (const float*)d_in[4];
    const float* cc  = (const float*)d_in[5];
    const float* ct  = (const float*)d_in[6];
    const float* crt = (const float*)d_in[7];

    static int attr_done = 0;
    if (!attr_done) {
        cudaFuncSetAttribute(raster_kernel,
                             cudaFuncAttributeMaxDynamicSharedMemorySize,
                             RASTER_SMEM);
        attr_done = 1;
    }
    setup_kernel<<<1, 512>>>(v, f, cf, cc, ct, crt);
    raster_kernel<<<NPIX / 32, 256, RASTER_SMEM>>>(f, vc, bg, (float*)d_out);
}

// round 13
// speedup vs baseline: 2.4000x; 1.0128x over previous
#include <cuda_runtime.h>

#define WIMG 128
#define HIMG 128
#define NV   512
#define NF   1024
#define NPIX (WIMG * HIMG)
#define RASTER_SMEM 53504   // 48K tri + 4K list + 64 counter/pad

// ---- scratch (no allocations allowed) ----
__device__ float4 g_tri0[NF];        // (signmask, area, inv_area, za)
__device__ float4 g_tri1[NF];        // (ax, ay, bx, by)
__device__ float4 g_tri2[NF];        // (cx, cy, zb, zc)
__device__ unsigned int g_bb[NF];    // packed bbox u8x4
__device__ float  g_iw[NV];

__device__ __forceinline__ float fm(float a, float b) { return __fmul_rn(a, b); }
__device__ __forceinline__ float fa(float a, float b) { return __fadd_rn(a, b); }
__device__ __forceinline__ float fs(float a, float b) { return __fsub_rn(a, b); }
__device__ __forceinline__ float fd(float a, float b) { return __fdiv_rn(a, b); }
__device__ __forceinline__ float ff3(float a, float b, float c) { return __fmaf_rn(a, b, c); }

// XLA-contracted edge/area form: a*b - c*d  ->  fma(a, b, -(c*d))
__device__ __forceinline__ float edge_fn(float a, float b, float c, float d) {
    return ff3(a, b, -fm(c, d));
}

// ================= setup: one block, 512 threads =================
__global__ void setup_kernel(const float* __restrict__ v,
                             const int* __restrict__ f,
                             const float* __restrict__ cf,
                             const float* __restrict__ cc,
                             const float* __restrict__ ct,
                             const float* __restrict__ crt) {
    __shared__ float sM[16];
    __shared__ float sxs[NV], sys[NV], szn[NV];
    int t = threadIdx.x;

    if (t < 32) {
        // ---- Rodrigues ----
        float rx = crt[0], ry = crt[1], rz = crt[2];
        float ssq = fa(fa(fm(rx, rx), fm(ry, ry)), fm(rz, rz));
        float theta = __fsqrt_rn(fa(ssq, 1e-12f));
        float kx = fd(rx, theta), ky = fd(ry, theta), kz = fd(rz, theta);
        float K[3][3] = {{0.f, -kz, ky}, {kz, 0.f, -kx}, {-ky, kx, 0.f}};
        float KK[3][3];
        #pragma unroll
        for (int i = 0; i < 3; i++)
            #pragma unroll
            for (int j = 0; j < 3; j++) {
                float s = fm(K[i][0], K[0][j]);
                s = ff3(K[i][1], K[1][j], s);
                s = ff3(K[i][2], K[2][j], s);
                KK[i][j] = s;
            }
        float sth = sinf(theta), cth1 = fs(1.0f, cosf(theta));
        float R[3][3];
        #pragma unroll
        for (int i = 0; i < 3; i++)
            #pragma unroll
            for (int j = 0; j < 3; j++) {
                float e = (i == j) ? 1.0f : 0.0f;
                R[i][j] = ff3(cth1, KK[i][j], ff3(sth, K[i][j], e));
            }
        float Mr[4][4] = {{0}}, Mt[4][4] = {{0}};
        #pragma unroll
        for (int i = 0; i < 4; i++) { Mr[i][i] = 1.f; Mt[i][i] = 1.f; }
        #pragma unroll
        for (int i = 0; i < 3; i++)
            #pragma unroll
            for (int j = 0; j < 3; j++) Mr[i][j] = R[j][i];
        Mt[3][0] = ct[0]; Mt[3][1] = ct[1]; Mt[3][2] = ct[2];
        float Vw[4][4];
        #pragma unroll
        for (int i = 0; i < 4; i++)
            #pragma unroll
            for (int j = 0; j < 4; j++) {
                float s = fm(Mr[i][0], Mt[0][j]);
                s = ff3(Mr[i][1], Mt[1][j], s);
                s = ff3(Mr[i][2], Mt[2][j], s);
                s = ff3(Mr[i][3], Mt[3][j], s);
                Vw[i][j] = s;
            }
        float ffv = fm(0.5f, fa(cf[0], cf[1]));
        float nf = fd(0.1f, ffv);
        float cx0 = fa(cc[0], 0.5f);
        float right  = fm(fs(128.0f, cx0), nf);
        float left   = -fm(cx0, nf);
        float top    = fm(fa(cc[1], 0.5f), nf);
        float bottom = -fm(fa(fs(128.0f, cc[1]), 0.5f), nf);
        float P[4][4] = {{0}};
        P[0][0] = fd(0.2f, fs(right, left));
        P[1][1] = fd(0.2f, fs(top, bottom));
        P[2][0] = fd(fa(right, left), fs(right, left));
        P[2][1] = fd(fa(top, bottom), fs(top, bottom));
        P[2][2] = (float)(-(10.0 + 0.1) / (10.0 - 0.1));
        P[2][3] = -1.0f;
        P[3][2] = (float)(-2.0 * 10.0 * 0.1 / (10.0 - 0.1));
        #pragma unroll
        for (int i = 0; i < 4; i++)
            #pragma unroll
            for (int j = 0; j < 4; j++) {
                float s = fm(Vw[i][0], P[0][j]);
                s = ff3(Vw[i][1], P[1][j], s);
                s = ff3(Vw[i][2], P[2][j], s);
                s = ff3(Vw[i][3], P[3][j], s);
                if (t == 0) sM[i * 4 + j] = s;
            }
    }
    __syncthreads();

    // ---- vertex transform (1 per thread) ----
    if (t < NV) {
        float vx = v[3 * t], vy = v[3 * t + 1], vz = v[3 * t + 2];
        float c[4];
        #pragma unroll
        for (int j = 0; j < 4; j++) {
            float s = fm(vx, sM[0 * 4 + j]);
            s = ff3(vy, sM[1 * 4 + j], s);
            s = ff3(vz, sM[2 * 4 + j], s);
            s = ff3(1.0f, sM[3 * 4 + j], s);
            c[j] = s;
        }
        int vld = (c[3] > 1e-8f) ? 1 : 0;
        float ws = vld ? c[3] : 1.0f;
        float nx = fd(c[0], ws), ny = fd(c[1], ws), nz = fd(c[2], ws);
        sxs[t] = fm(ff3(nx, 0.5f, 0.5f), 128.0f);   // pow2 scales: exact
        sys[t] = fm(fs(0.5f, fm(ny, 0.5f)), 128.0f);
        szn[t] = vld ? nz : __int_as_float(0x7FC00000);  // NaN marks invalid
        g_iw[t] = fd(1.0f, ws);
    }
    __syncthreads();

    // ---- triangle setup (2 per thread) ----
    for (int k = t; k < NF; k += 512) {
        int i0 = f[3 * k], i1 = f[3 * k + 1], i2 = f[3 * k + 2];
        float ax = sxs[i0], ay = sys[i0];
        float bx = sxs[i1], by = sys[i1];
        float cx = sxs[i2], cy = sys[i2];
        float area = edge_fn(fs(bx, ax), fs(cy, ay), fs(by, ay), fs(cx, ax));
        float za = szn[i0], zb = szn[i1], zc = szn[i2];
        bool zok = (za == za) && (zb == zb) && (zc == zc);
        bool ok = zok && (fabsf(area) > 1e-8f);
        float nanf = __int_as_float(0x7FC00000);
        float area_s = ok ? area : nanf;        // poisons exact path
        float ia     = ok ? fd(1.0f, area) : nanf;
        // sign mask: XOR with w flips sign iff area < 0 (invalid tris culled)
        unsigned int sgn = (ok && area < 0.0f) ? 0x80000000u : 0u;

        // conservative pixel-space bbox (u8x4); lo>hi => always cull
        unsigned int packed = 0x000000FFu;      // ixlo=255 > ixhi=0
        if (ok) {
            float xmin = fminf(ax, fminf(bx, cx));
            float xmax = fmaxf(ax, fmaxf(bx, cx));
            float ymin = fminf(ay, fminf(by, cy));
            float ymax = fmaxf(ay, fmaxf(by, cy));
            if (!(xmax < 0.5f || xmin > 127.5f || ymax < 0.5f || ymin > 127.5f)) {
                int ixlo = (int)floorf(fminf(fmaxf(xmin - 0.5f, 0.f), 127.f));
                int ixhi = (int)ceilf (fminf(fmaxf(xmax - 0.5f, 0.f), 127.f));
                int iylo = (int)floorf(fminf(fmaxf(ymin - 0.5f, 0.f), 127.f));
                int iyhi = (int)ceilf (fminf(fmaxf(ymax - 0.5f, 0.f), 127.f));
                packed = (unsigned)ixlo | ((unsigned)ixhi << 8) |
                         ((unsigned)iylo << 16) | ((unsigned)iyhi << 24);
            }
        }
        g_bb[k]   = packed;
        g_tri0[k] = make_float4(__uint_as_float(sgn), area_s, ia, za);
        g_tri1[k] = make_float4(ax, ay, bx, by);
        g_tri2[k] = make_float4(cx, cy, zb, zc);
    }
}

// evaluate one triangle up to the candidate screen (no divides)
__device__ __forceinline__ void eval_tri(
    const float4* __restrict__ T0, const float4* __restrict__ T1,
    const float4* __restrict__ T2, int idx, float x, float y, float bd,
    bool& cand, float& w0, float& w1, float& w2,
    float& area, float& za, float& zb, float& zc)
{
    float4 p0 = T0[idx];
    unsigned int sgn = __float_as_uint(p0.x);
    area = p0.y; float ia = p0.z; za = p0.w;
    float4 p1 = T1[idx];
    float4 p2 = T2[idx];
    float ax = p1.x, ay = p1.y, bxv = p1.z, byv = p1.w;
    float cx = p2.x, cy = p2.y; zb = p2.z; zc = p2.w;

    // contracted reference edges: (qx-px)*(y-py) - (qy-py)*(x-px)
    w0 = edge_fn(fs(cx, bxv), fs(y, byv), fs(cy, byv), fs(x, bxv));
    w1 = edge_fn(fs(ax, cx),  fs(y, cy),  fs(ay, cy),  fs(x, cx));
    w2 = edge_fn(fs(bxv, ax), fs(y, ay),  fs(byv, ay), fs(x, ax));

    // exact sign tests: sign(w/area) == sign(sgn-flipped w), incl. +-0
    float t0 = __uint_as_float(__float_as_uint(w0) ^ sgn);
    float t1 = __uint_as_float(__float_as_uint(w1) ^ sgn);
    float t2 = __uint_as_float(__float_as_uint(w2) ^ sgn);
    bool inside = (t0 >= 0.0f) & (t1 >= 0.0f) & (t2 >= 0.0f);

    // cheap depth screen (conservative filter; exact path re-verifies)
    cand = false;
    if (inside) {
        float zs  = ff3(w2, zc, ff3(w0, za, fm(w1, zb)));
        float z_t = fm(zs, ia);                 // NaN ia -> cand false
        cand = (z_t >= -1.0001f) & (z_t <= 1.0001f) & (z_t < bd + 1e-4f);
    }
}

// ================= raster: 512 blocks x 256 threads =================
// Block = 8x4 pixel tile. Phase A: block-wide bbox cull of all 1024 tris
// into a compacted smem list (warp-aggregated). Phase B: 8 warps walk the
// list in interleaved pairs (balanced), lexicographic (z, idx) accept.
extern "C" __global__ void __launch_bounds__(256, 3)
raster_kernel(const int* __restrict__ f,
              const float* __restrict__ vc,
              const float* __restrict__ bg,
              float* __restrict__ out) {
    extern __shared__ char smem[];
    float4* T0    = (float4*)(smem);
    float4* T1    = (float4*)(smem + 16384);
    float4* T2    = (float4*)(smem + 32768);
    int*    LIST  = (int*)(smem + 49152);       // [1024]
    int*    COUNT = (int*)(smem + 53248);
    int t = threadIdx.x;

    if (t == 0) *COUNT = 0;
    #pragma unroll
    for (int j = t; j < NF; j += 256) {
        T0[j] = g_tri0[j];
        T1[j] = g_tri1[j];
        T2[j] = g_tri2[j];
    }
    __syncthreads();

    int lane = t & 31;
    int pg   = blockIdx.x;                      // tile id: 16 x-tiles, 32 y-tiles
    int tx0  = (pg & 15) * 8;
    int ty0  = (pg >> 4) * 4;
    float x = (float)(tx0 + (lane & 7)) + 0.5f;
    float y = (float)(ty0 + (lane >> 3)) + 0.5f;

    // ---- Phase A: block-wide cull + compaction ----
    #pragma unroll
    for (int r = 0; r < NF / 256; ++r) {
        int k = r * 256 + t;
        unsigned int bbv = g_bb[k];             // coalesced LDG
        int ixlo = bbv & 255, ixhi = (bbv >> 8) & 255;
        int iylo = (bbv >> 16) & 255, iyhi = (bbv >> 24) & 255;
        bool pass = !(iyhi < ty0 || iylo > ty0 + 3 ||
                      ixhi < tx0 || ixlo > tx0 + 7);
        unsigned int m = __ballot_sync(0xffffffffu, pass);
        int cnt = __popc(m);
        int wbase = 0;
        if (lane == 0 && cnt) wbase = atomicAdd(COUNT, cnt);
        wbase = __shfl_sync(0xffffffffu, wbase, 0);
        if (pass)
            LIST[wbase + __popc(m & ((1u << lane) - 1u))] = k;
    }
    __syncthreads();
    int nsurv = *COUNT;

    // ---- Phase B: balanced pairwise walk ----
    int wi = t >> 5;
    float bd = __int_as_float(0x7f800000);      // +inf
    int   bi = 0x7fffffff;
    float bb0 = 0.f, bb1 = 0.f, bb2 = 0.f;

    for (int i = 2 * wi; i < nsurv; i += 16) {
        int idx1 = LIST[i];                     // warp-uniform -> broadcast
        bool has2 = (i + 1 < nsurv);
        int idx2 = has2 ? LIST[i + 1] : idx1;

        bool c1, c2;
        float aw0, aw1, aw2, aar, aza, azb, azc;
        float bw0, bw1, bw2, bar, bza, bzb, bzc;
        eval_tri(T0, T1, T2, idx1, x, y, bd, c1, aw0, aw1, aw2, aar, aza, azb, azc);
        eval_tri(T0, T1, T2, idx2, x, y, bd, c2, bw0, bw1, bw2, bar, bza, bzb, bzc);
        c2 = c2 && has2;

        if (__any_sync(0xffffffffu, c1 | c2)) {
            if (c1) {                           // exact path, bit-identical
                float b0 = fd(aw0, aar);
                float b1 = fd(aw1, aar);
                float b2 = fd(aw2, aar);
                float z = ff3(b2, azc, ff3(b0, aza, fm(b1, azb)));
                if (z >= -1.0f && z <= 1.0f &&
                    (z < bd || (z == bd && idx1 < bi))) {
                    bd = z; bi = idx1; bb0 = b0; bb1 = b1; bb2 = b2;
                }
            }
            if (c2) {
                float b0 = fd(bw0, bar);
                float b1 = fd(bw1, bar);
                float b2 = fd(bw2, bar);
                float z = ff3(b2, bzc, ff3(b0, bza, fm(b1, bzb)));
                if (z >= -1.0f && z <= 1.0f &&
                    (z < bd || (z == bd && idx2 < bi))) {
                    bd = z; bi = idx2; bb0 = b0; bb1 = b1; bb2 = b2;
                }
            }
        }
    }

    // ---- merge 8 warps via smem (reuse T0 region after sync) ----
    __syncthreads();
    float* mz = (float*)smem;                   // [256]
    int*   mi = (int*)(smem + 1024);            // [256]
    float* m0 = (float*)(smem + 2048);          // [256]
    float* m1 = (float*)(smem + 3072);          // [256]
    float* m2 = (float*)(smem + 4096);          // [256]
    mz[t] = bd; mi[t] = bi; m0[t] = bb0; m1[t] = bb1; m2[t] = bb2;
    __syncthreads();

    if (t < 32) {
        #pragma unroll
        for (int w = 1; w < 8; ++w) {
            float zo = mz[w * 32 + t];
            int   io = mi[w * 32 + t];
            if (zo < bd || (zo == bd && io < bi)) {
                bd = zo; bi = io;
                bb0 = m0[w * 32 + t]; bb1 = m1[w * 32 + t]; bb2 = m2[w * 32 + t];
            }
        }

        float r, g, b;
        if (bd <= 1.0f) {
            int i0 = f[3 * bi], i1 = f[3 * bi + 1], i2 = f[3 * bi + 2];
            float k0 = fm(bb0, g_iw[i0]);
            float k1 = fm(bb1, g_iw[i1]);
            float k2 = fm(bb2, g_iw[i2]);
            float den = fa(fa(k0, k1), k2);
            if (!(fabsf(den) > 1e-8f)) den = 1.0f;
            r = fd(ff3(k2, vc[3 * i2 + 0], ff3(k0, vc[3 * i0 + 0], fm(k1, vc[3 * i1 + 0]))), den);
            g = fd(ff3(k2, vc[3 * i2 + 1], ff3(k0, vc[3 * i0 + 1], fm(k1, vc[3 * i1 + 1]))), den);
            b = fd(ff3(k2, vc[3 * i2 + 2], ff3(k0, vc[3 * i0 + 2], fm(k1, vc[3 * i1 + 2]))), den);
        } else {
            r = bg[0]; g = bg[1]; b = bg[2];
        }
        int p = (ty0 + (t >> 3)) * WIMG + tx0 + (t & 7);
        out[p * 3 + 0] = r;
        out[p * 3 + 1] = g;
        out[p * 3 + 2] = b;
    }
}

extern "C" void kernel_launch(void* const* d_in, const int* in_sizes, int n_in,
                              void* d_out, int out_size) {
    const float* v   = (const float*)d_in[0];
    const float* vc  = (const float*)d_in[1];
    const int*   f   = (const int*)d_in[2];
    const float* bg  = (const float*)d_in[3];
    const float* cf  = (const float*)d_in[4];
    const float* cc  = (const float*)d_in[5];
    const float* ct  = (const float*)d_in[6];
    const float* crt = (const float*)d_in[7];

    static int attr_done = 0;
    if (!attr_done) {
        cudaFuncSetAttribute(raster_kernel,
                             cudaFuncAttributeMaxDynamicSharedMemorySize,
                             RASTER_SMEM);
        attr_done = 1;
    }
    setup_kernel<<<1, 512>>>(v, f, cf, cc, ct, crt);
    raster_kernel<<<NPIX / 32, 256, RASTER_SMEM>>>(f, vc, bg, (float*)d_out);
}